// round 2
// baseline (speedup 1.0000x reference)
#include <cuda_runtime.h>
#include <math_constants.h>

#define NTH 256
#define NWARPS (NTH / 32)
#define MAXK 512

// Cost matrix C[i*m + j] = -IoU(target_i, proposal_j), fp32 (exact per-op match
// with the reference's fp32 computation; widened to fp64 inside the solver).
__device__ float g_C[1 << 17];  // 131072 floats >= 100*300

__global__ void iou_cost_kernel(const float* __restrict__ tgt,
                                const float* __restrict__ prp,
                                int N, int M) {
    int idx = blockIdx.x * blockDim.x + threadIdx.x;
    if (idx >= N * M) return;
    int i = idx / M, j = idx - i * M;

    float ax0 = tgt[4 * i + 0], ay0 = tgt[4 * i + 1];
    float ax1 = tgt[4 * i + 2], ay1 = tgt[4 * i + 3];
    float bx0 = prp[4 * j + 0], by0 = prp[4 * j + 1];
    float bx1 = prp[4 * j + 2], by1 = prp[4 * j + 3];

    // Explicit round-to-nearest intrinsics: prevents FMA contraction so the
    // fp32 bits match the reference's elementwise ops exactly.
    float area_a = __fmul_rn(__fsub_rn(ax1, ax0), __fsub_rn(ay1, ay0));
    float area_b = __fmul_rn(__fsub_rn(bx1, bx0), __fsub_rn(by1, by0));
    float ltx = fmaxf(ax0, bx0), lty = fmaxf(ay0, by0);
    float rbx = fminf(ax1, bx1), rby = fminf(ay1, by1);
    float wx = fmaxf(__fsub_rn(rbx, ltx), 0.0f);
    float wy = fmaxf(__fsub_rn(rby, lty), 0.0f);
    float inter = __fmul_rn(wx, wy);
    float uni = __fsub_rn(__fadd_rn(area_a, area_b), inter);
    g_C[idx] = -__fdiv_rn(inter, uni);
}

// Exact Jonker-Volgenant shortest-augmenting-path LAP on the (n+m)x(n+m)
// extended matrix, replicating the reference bit-for-bit in fp64:
//   Ce[i][j] = C[i][j]        (i<n, j<m)
//            = cost_limit/2   (exactly one of i>=n, j>=m)   [= -0.25]
//            = 0              (i>=n, j>=m)
// Single block; the per-Dijkstra-step O(k) column relax + argmin is parallel,
// the step/row loops are sequential (steered by thread 0 via shared scalars).
__global__ void __launch_bounds__(NTH, 1)
lapjv_kernel(int n, int m, float* __restrict__ out) {
    __shared__ double u[MAXK], v[MAXK], spc[MAXK];
    __shared__ int path[MAXK], col4row[MAXK], row4col[MAXK];
    __shared__ unsigned char SC[MAXK], SR[MAXK];
    __shared__ double wv[NWARPS];
    __shared__ int wi[NWARPS];
    __shared__ int s_i, s_sink;
    __shared__ double s_minVal;

    const int tid = threadIdx.x;
    const int k = n + m;
    const double half_cl = -0.25;  // cost_limit(-0.5) / 2

    for (int j = tid; j < k; j += NTH) {
        u[j] = 0.0; v[j] = 0.0;
        col4row[j] = -1; row4col[j] = -1;
    }
    __syncthreads();

    for (int cur = 0; cur < k; ++cur) {
        for (int j = tid; j < k; j += NTH) {
            spc[j] = CUDART_INF;
            path[j] = -1;
            SC[j] = 0;
            SR[j] = 0;
        }
        if (tid == 0) { s_i = cur; s_minVal = 0.0; s_sink = -1; }
        __syncthreads();

        // Dijkstra over columns until an unmatched column becomes the minimum.
        while (true) {
            const int i = s_i;
            const double minVal = s_minVal;
            if (tid == 0) SR[i] = 1;
            const double ui = u[i];

            double best = CUDART_INF;
            int bidx = 0x7fffffff;

            if (i < n) {
                const float* Crow = &g_C[i * m];
                for (int j = tid; j < k; j += NTH) {
                    if (!SC[j]) {
                        double ce = (j < m) ? (double)Crow[j] : half_cl;
                        // exact reference op order: ((minVal + ce) - u[i]) - v[j]
                        double red = ((minVal + ce) - ui) - v[j];
                        double s = spc[j];
                        if (red < s) { s = red; spc[j] = red; path[j] = i; }
                        // strict '<' + ascending j per thread => first-min kept
                        if (s < best) { best = s; bidx = j; }
                    }
                }
            } else {
                for (int j = tid; j < k; j += NTH) {
                    if (!SC[j]) {
                        double ce = (j < m) ? half_cl : 0.0;
                        double red = ((minVal + ce) - ui) - v[j];
                        double s = spc[j];
                        if (red < s) { s = red; spc[j] = red; path[j] = i; }
                        if (s < best) { best = s; bidx = j; }
                    }
                }
            }

            // argmin reduction, tie-break on smallest column index
            // (matches np.argmin first-occurrence over unscanned columns)
            #pragma unroll
            for (int off = 16; off; off >>= 1) {
                double ob = __shfl_down_sync(0xffffffffu, best, off);
                int oi = __shfl_down_sync(0xffffffffu, bidx, off);
                if (ob < best || (ob == best && oi < bidx)) { best = ob; bidx = oi; }
            }
            if ((tid & 31) == 0) { wv[tid >> 5] = best; wi[tid >> 5] = bidx; }
            __syncthreads();

            if (tid == 0) {
                double bb = wv[0]; int bj = wi[0];
                #pragma unroll
                for (int w = 1; w < NWARPS; ++w)
                    if (wv[w] < bb || (wv[w] == bb && wi[w] < bj)) { bb = wv[w]; bj = wi[w]; }
                s_minVal = spc[bj];
                SC[bj] = 1;
                int r = row4col[bj];
                if (r < 0) s_sink = bj; else s_i = r;
            }
            __syncthreads();
            if (s_sink >= 0) break;
        }

        // Dual updates (parallel), exactly as the reference:
        //   u[cur] += minVal
        //   u[ii]  += minVal - spc[col4row[ii]]   for scanned rows ii != cur
        //   v[j]   -= minVal - spc[j]             for scanned columns j
        const double minVal = s_minVal;
        for (int ii = tid; ii < k; ii += NTH) {
            if (SR[ii]) {
                if (ii == cur) u[ii] = u[ii] + minVal;
                else           u[ii] = u[ii] + (minVal - spc[col4row[ii]]);
            }
        }
        for (int j = tid; j < k; j += NTH) {
            if (SC[j]) v[j] = v[j] - (minVal - spc[j]);
        }
        __syncthreads();

        // Augment along predecessor path (sequential, integer-only).
        if (tid == 0) {
            int j = s_sink;
            while (true) {
                int i2 = path[j];
                row4col[j] = i2;
                int nxt = col4row[i2];
                col4row[i2] = j;
                j = nxt;
                if (i2 == cur) break;
            }
        }
        __syncthreads();
    }

    // Outputs (as float32 — the harness's __output__ dtype):
    //   out[0:n]    = row = col4row[:n]  (>=m -> -1)
    //   out[n:n+m]  = col = row4col[:m]  (>=n -> -1)
    for (int i = tid; i < n; i += NTH) {
        int r = col4row[i];
        out[i] = (r >= m) ? -1.0f : (float)r;
    }
    for (int j = tid; j < m; j += NTH) {
        int c = row4col[j];
        out[n + j] = (c >= n) ? -1.0f : (float)c;
    }
}

extern "C" void kernel_launch(void* const* d_in, const int* in_sizes, int n_in,
                              void* d_out, int out_size) {
    const float* tgt = (const float*)d_in[0];   // target_bbox   [N,4] fp32
    const float* prp = (const float*)d_in[1];   // proposal_bbox [M,4] fp32
    int N = in_sizes[0] / 4;
    int M = in_sizes[1] / 4;
    int nm = N * M;

    iou_cost_kernel<<<(nm + 255) / 256, 256>>>(tgt, prp, N, M);
    lapjv_kernel<<<1, NTH>>>(N, M, (float*)d_out);
}

// round 3
// speedup vs baseline: 74.1573x; 74.1573x over previous
#include <cuda_runtime.h>
#include <math_constants.h>

#define MAXK 512        // reduced problem size bound (n'+m' <= n+m = 400)
#define MAXE 30016      // edge list bound (worst case: all pairs)
#define SHE  4096       // shared-memory edge cache size
#define FULLMASK 0xffffffffu

// -------- device globals (no allocation allowed) --------
__device__ int   g_ne;
__device__ int   g_er[MAXE];
__device__ int   g_ec[MAXE];
__device__ float g_ew[MAXE];      // C_ij = -IoU (fp32, exact)
__device__ int   g_rowhas[MAXK];
__device__ int   g_colhas[MAXK];

__global__ void reset_kernel() {
    int t = threadIdx.x;
    if (t == 0) g_ne = 0;
    for (int x = t; x < MAXK; x += blockDim.x) { g_rowhas[x] = 0; g_colhas[x] = 0; }
}

// Exact fp32 IoU (round-to-nearest intrinsics block FMA contraction so bits
// match the reference's elementwise fp32 ops). Emits only IoU > 0.5 edges:
// the padded lapjv(cost_limit=-0.5) optimum provably never matches any other
// pair, so the output depends only on this sparse subgraph.
__global__ void iou_edge_kernel(const float* __restrict__ tgt,
                                const float* __restrict__ prp,
                                int N, int M) {
    int idx = blockIdx.x * blockDim.x + threadIdx.x;
    if (idx >= N * M) return;
    int i = idx / M, j = idx - i * M;

    float ax0 = tgt[4 * i + 0], ay0 = tgt[4 * i + 1];
    float ax1 = tgt[4 * i + 2], ay1 = tgt[4 * i + 3];
    float bx0 = prp[4 * j + 0], by0 = prp[4 * j + 1];
    float bx1 = prp[4 * j + 2], by1 = prp[4 * j + 3];

    float area_a = __fmul_rn(__fsub_rn(ax1, ax0), __fsub_rn(ay1, ay0));
    float area_b = __fmul_rn(__fsub_rn(bx1, bx0), __fsub_rn(by1, by0));
    float ltx = fmaxf(ax0, bx0), lty = fmaxf(ay0, by0);
    float rbx = fminf(ax1, bx1), rby = fminf(ay1, by1);
    float wx = fmaxf(__fsub_rn(rbx, ltx), 0.0f);
    float wy = fmaxf(__fsub_rn(rby, lty), 0.0f);
    float inter = __fmul_rn(wx, wy);
    float uni = __fsub_rn(__fadd_rn(area_a, area_b), inter);
    float iou = __fdiv_rn(inter, uni);

    if (iou > 0.5f) {
        int pos = atomicAdd(&g_ne, 1);
        if (pos < MAXE) {
            g_er[pos] = i;
            g_ec[pos] = j;
            g_ew[pos] = -iou;          // C_ij, exact fp32
        }
        g_rowhas[i] = 1;               // benign races (flag set)
        g_colhas[j] = 1;
    }
}

// Exact fp64 Jonker-Volgenant on the REDUCED extended matrix:
//   Ce[r][c] = C_rc + 0.5   (edge, r<n', c<m')
//            = 1e30         (non-edge real pair — never optimal)
//            = 0            (any dummy row/col entry)
// Optimum == the reference's padded-LAP optimum restricted to real pairs
// (unique a.s. for continuous random costs). Single warp, no block barriers.
__global__ void __launch_bounds__(32, 1)
solve_kernel(int n, int m, float* __restrict__ out) {
    __shared__ double u[MAXK], v[MAXK], spc[MAXK], row_ce[MAXK];
    __shared__ int path[MAXK], col4row[MAXK], row4col[MAXK];
    __shared__ unsigned char SC[MAXK], SR[MAXK];
    __shared__ int rowmap[128], rinv[128];
    __shared__ int colmap[MAXK], cinv[MAXK];
    __shared__ short s_er[SHE], s_ec[SHE];
    __shared__ int s_np, s_mp, s_E;

    const int tid = threadIdx.x;

    // ---- compact touched rows/cols (tiny, thread 0) ----
    if (tid == 0) {
        int np = 0;
        for (int i = 0; i < n; ++i) {
            if (g_rowhas[i]) { rinv[i] = np; rowmap[np++] = i; }
            else rinv[i] = -1;
        }
        int mp = 0;
        for (int j = 0; j < m; ++j) {
            if (g_colhas[j]) { cinv[j] = mp; colmap[mp++] = j; }
            else cinv[j] = -1;
        }
        int E = g_ne; if (E > MAXE) E = MAXE;
        s_np = np; s_mp = mp; s_E = E;
    }
    __syncwarp();

    const int np = s_np, mp = s_mp, E = s_E;
    const int k = np + mp;
    const bool cache = (E <= SHE);

    if (cache) {
        for (int e = tid; e < E; e += 32) {
            s_er[e] = (short)rinv[g_er[e]];
            s_ec[e] = (short)cinv[g_ec[e]];
        }
    }
    for (int x = tid; x < k; x += 32) {
        u[x] = 0.0; v[x] = 0.0;
        col4row[x] = -1; row4col[x] = -1;
    }
    __syncwarp();

    for (int cur = 0; cur < k; ++cur) {
        for (int x = tid; x < k; x += 32) {
            spc[x] = CUDART_INF; path[x] = -1; SC[x] = 0; SR[x] = 0;
        }
        __syncwarp();

        int i = cur;            // identical in all lanes
        double minVal = 0.0;
        int sink = -1;

        while (sink < 0) {
            if (tid == 0) SR[i] = 1;

            // materialize current row's costs (real rows only)
            if (i < np) {
                for (int j = tid; j < k; j += 32)
                    row_ce[j] = (j < mp) ? 1e30 : 0.0;
                __syncwarp();
                if (cache) {
                    for (int e = tid; e < E; e += 32)
                        if (s_er[e] == i) row_ce[s_ec[e]] = (double)g_ew[e] + 0.5;
                } else {
                    for (int e = tid; e < E; e += 32)
                        if (rinv[g_er[e]] == i) row_ce[cinv[g_ec[e]]] = (double)g_ew[e] + 0.5;
                }
                __syncwarp();
            }

            const double ui = u[i];
            double best = CUDART_INF;
            int bidx = 0x7fffffff;

            for (int j = tid; j < k; j += 32) {
                if (!SC[j]) {
                    double ce = (i < np) ? row_ce[j] : 0.0;
                    double red = ((minVal + ce) - ui) - v[j];
                    double s = spc[j];
                    if (red < s) { s = red; spc[j] = red; path[j] = i; }
                    if (s < best) { best = s; bidx = j; }
                }
            }

            // butterfly min-reduce with lowest-index tie-break (all lanes converge)
            #pragma unroll
            for (int off = 16; off; off >>= 1) {
                double ob = __shfl_xor_sync(FULLMASK, best, off);
                int oi = __shfl_xor_sync(FULLMASK, bidx, off);
                if (ob < best || (ob == best && oi < bidx)) { best = ob; bidx = oi; }
            }

            minVal = best;                 // == spc[bidx]
            if (tid == 0) SC[bidx] = 1;
            __syncwarp();
            int r = row4col[bidx];
            if (r < 0) sink = bidx; else i = r;
        }

        __syncwarp();  // make relax-phase spc/SR writes visible cross-lane

        // dual updates
        for (int x = tid; x < k; x += 32) {
            if (SR[x]) u[x] += (x == cur) ? minVal : (minVal - spc[col4row[x]]);
            if (SC[x]) v[x] -= (minVal - spc[x]);
        }
        __syncwarp();

        // augment (integer-only, lane 0)
        if (tid == 0) {
            int j = sink;
            while (true) {
                int i2 = path[j];
                row4col[j] = i2;
                int nxt = col4row[i2];
                col4row[i2] = j;
                j = nxt;
                if (i2 == cur) break;
            }
        }
        __syncwarp();
    }

    // ---- outputs (float32): out[0:n]=row, out[n:n+m]=col, -1 default ----
    for (int x = tid; x < n + m; x += 32) out[x] = -1.0f;
    __syncwarp();
    for (int r = tid; r < np; r += 32) {
        int j = col4row[r];
        if (j >= 0 && j < mp) {
            int oi = rowmap[r], oj = colmap[j];
            out[oi] = (float)oj;
            out[n + oj] = (float)oi;
        }
    }
}

extern "C" void kernel_launch(void* const* d_in, const int* in_sizes, int n_in,
                              void* d_out, int out_size) {
    const float* tgt = (const float*)d_in[0];   // target_bbox   [N,4] fp32
    const float* prp = (const float*)d_in[1];   // proposal_bbox [M,4] fp32
    int N = in_sizes[0] / 4;
    int M = in_sizes[1] / 4;
    int nm = N * M;

    reset_kernel<<<1, 256>>>();
    iou_edge_kernel<<<(nm + 255) / 256, 256>>>(tgt, prp, N, M);
    solve_kernel<<<1, 32>>>(N, M, (float*)d_out);
}

// round 4
// speedup vs baseline: 814.7115x; 10.9863x over previous
#include <cuda_runtime.h>
#include <math_constants.h>

#define NTH   1024
#define NMAX  128
#define MMAX  320
#define ECAP  2048      // shared-memory edge capacity
#define MAXE  30720     // >= n*m worst case
#define FULLMASK 0xffffffffu

// global fallback storage (no allocations allowed)
__device__ int   g_eij[MAXE];
__device__ float g_ew[MAXE];
__device__ short g_ccol[MAXE];
__device__ float g_cw[MAXE];

// Single fused kernel: exact fp32 IoU -> sparse IoU>0.5 edge list -> CSR ->
// exact fp64 successive-shortest-path min-cost matching with per-row slack
// (provably equivalent to lap.lapjv(C, cost_limit=-0.5, extend_cost=True)
// restricted to real pairs; the optimum is unique a.s. for continuous costs,
// so any exact solver reproduces the reference output).
__global__ void __launch_bounds__(NTH, 1)
matcher_kernel(const float* __restrict__ tgt, const float* __restrict__ prp,
               int n, int m, float* __restrict__ out) {
    __shared__ int   s_eij[ECAP];
    __shared__ float s_ew[ECAP];
    __shared__ short cs_col[ECAP];
    __shared__ float cs_w[ECAP];
    __shared__ int   cs_off[NMAX + 1];
    __shared__ int   deg[NMAX];
    __shared__ int   cur_off[NMAX];
    __shared__ unsigned char colhas[MMAX];
    __shared__ short colmap[MMAX], cinv[MMAX];
    __shared__ short rowlist[NMAX];
    __shared__ double u[NMAX], v[MMAX], spc[MMAX];
    __shared__ short path[MMAX], row4col[MMAX];
    __shared__ short col4row[NMAX];
    __shared__ unsigned char SC[MMAX];
    __shared__ short srl[NMAX];
    __shared__ int s_ne, s_nr, s_mp;

    const int tid = threadIdx.x;

    if (tid == 0) s_ne = 0;
    for (int x = tid; x < m; x += NTH) colhas[x] = 0;
    for (int x = tid; x < n; x += NTH) deg[x] = 0;
    __syncthreads();

    // ---- phase 1: exact fp32 IoU, emit IoU>0.5 edges ----
    const int nm = n * m;
    for (int idx = tid; idx < nm; idx += NTH) {
        int i = idx / m, j = idx - i * m;
        float ax0 = __ldg(&tgt[4 * i + 0]), ay0 = __ldg(&tgt[4 * i + 1]);
        float ax1 = __ldg(&tgt[4 * i + 2]), ay1 = __ldg(&tgt[4 * i + 3]);
        float bx0 = __ldg(&prp[4 * j + 0]), by0 = __ldg(&prp[4 * j + 1]);
        float bx1 = __ldg(&prp[4 * j + 2]), by1 = __ldg(&prp[4 * j + 3]);

        // round-to-nearest intrinsics block FMA contraction: bits match reference
        float area_a = __fmul_rn(__fsub_rn(ax1, ax0), __fsub_rn(ay1, ay0));
        float area_b = __fmul_rn(__fsub_rn(bx1, bx0), __fsub_rn(by1, by0));
        float ltx = fmaxf(ax0, bx0), lty = fmaxf(ay0, by0);
        float rbx = fminf(ax1, bx1), rby = fminf(ay1, by1);
        float wx = fmaxf(__fsub_rn(rbx, ltx), 0.0f);
        float wy = fmaxf(__fsub_rn(rby, lty), 0.0f);
        float inter = __fmul_rn(wx, wy);
        float uni = __fsub_rn(__fadd_rn(area_a, area_b), inter);
        float iou = __fdiv_rn(inter, uni);

        if (iou > 0.5f) {
            int pos = atomicAdd(&s_ne, 1);
            int pack = (i << 16) | j;
            if (pos < ECAP) { s_eij[pos] = pack; s_ew[pos] = -iou; }
            if (pos < MAXE) { g_eij[pos] = pack; g_ew[pos] = -iou; }
            atomicAdd(&deg[i], 1);
            colhas[j] = 1;
        }
    }
    __syncthreads();

    const int E = s_ne;
    const bool small = (E <= ECAP);

    // ---- compaction + CSR offsets (thread 0, tiny) ----
    if (tid == 0) {
        int mp = 0;
        for (int j = 0; j < m; ++j)
            if (colhas[j]) { cinv[j] = (short)mp; colmap[mp++] = (short)j; }
        s_mp = mp;
        int nr = 0, off = 0;
        for (int i = 0; i < n; ++i) {
            if (deg[i] > 0) rowlist[nr++] = (short)i;
            cs_off[i] = off; cur_off[i] = off; off += deg[i];
        }
        cs_off[n] = off;
        s_nr = nr;
    }
    __syncthreads();
    const int mp = s_mp, nr = s_nr;

    // ---- CSR scatter (all threads) ----
    if (small) {
        for (int e = tid; e < E; e += NTH) {
            int pk = s_eij[e]; int i = pk >> 16, j = pk & 0xffff;
            int p = atomicAdd(&cur_off[i], 1);
            cs_col[p] = cinv[j]; cs_w[p] = s_ew[e];
        }
    } else {
        int EE = (E > MAXE) ? MAXE : E;
        for (int e = tid; e < EE; e += NTH) {
            int pk = g_eij[e]; int i = pk >> 16, j = pk & 0xffff;
            int p = atomicAdd(&cur_off[i], 1);
            g_ccol[p] = cinv[j]; g_cw[p] = g_ew[e];
        }
    }
    __syncthreads();

    // ---- exact fp64 SSP min-cost matching with per-row slack (warp 0) ----
    if (tid < 32) {
        const short* Ccol = small ? cs_col : g_ccol;
        const float* Cw   = small ? cs_w   : g_cw;

        for (int x = tid; x < mp; x += 32) { v[x] = 0.0; row4col[x] = -1; }
        for (int x = tid; x < nr; x += 32) { u[x] = 0.0; col4row[x] = -1; }
        __syncwarp();

        for (int rr = 0; rr < nr; ++rr) {
            for (int x = tid; x < mp; x += 32) {
                spc[x] = CUDART_INF; SC[x] = 0; path[x] = -1;
            }
            __syncwarp();

            int i = rr;                     // compact row index (uniform)
            double shortest = 0.0;
            double spcD = CUDART_INF;       // label of the aggregated dummy sink
            int dpred = -1;
            int nsr = 0;
            int sink = -1;
            double minVal = 0.0;
            bool dummySink = false;

            while (true) {
                if (tid == 0) srl[nsr] = (short)i;
                nsr++;
                const double ui = u[i];

                // dummy ("stay unmatched") relax: w=0, v_dummy=0
                double dc = shortest - ui;
                if (dc < spcD) { spcD = dc; dpred = i; }

                // relax this row's edges (CSR)
                int io = rowlist[i];
                int b = cs_off[io], e2 = cs_off[io + 1];
                for (int e = b + tid; e < e2; e += 32) {
                    int j = Ccol[e];
                    if (!SC[j]) {
                        double red = shortest + ((double)Cw[e] + 0.5) - ui - v[j];
                        if (red < spc[j]) { spc[j] = red; path[j] = (short)i; }
                    }
                }
                __syncwarp();

                // argmin over unscanned columns
                double best = CUDART_INF; int bidx = 0x7fffffff;
                for (int j = tid; j < mp; j += 32)
                    if (!SC[j] && spc[j] < best) { best = spc[j]; bidx = j; }
                #pragma unroll
                for (int off = 16; off; off >>= 1) {
                    double ob = __shfl_xor_sync(FULLMASK, best, off);
                    int oi = __shfl_xor_sync(FULLMASK, bidx, off);
                    if (ob < best || (ob == best && oi < bidx)) { best = ob; bidx = oi; }
                }

                if (spcD < best) { dummySink = true; minVal = spcD; break; }
                minVal = best;
                if (tid == 0) SC[bidx] = 1;
                __syncwarp();
                int r4 = row4col[bidx];
                if (r4 < 0) { sink = bidx; break; }
                i = r4;
                shortest = minVal;
            }
            __syncwarp();

            // dual updates (JV form; keeps dummy edges feasible: u[i] <= 0)
            for (int t = tid; t < nsr; t += 32) {
                int ii = srl[t];
                if (ii == rr) u[ii] += minVal;
                else          u[ii] += minVal - spc[col4row[ii]];
            }
            for (int j = tid; j < mp; j += 32)
                if (SC[j]) v[j] -= minVal - spc[j];
            __syncwarp();

            // augment (lane 0, integer-only)
            if (tid == 0) {
                if (dummySink) {
                    int ii = dpred;
                    if (ii != rr) {
                        int j = col4row[ii];
                        col4row[ii] = -1;       // ii becomes unmatched
                        while (true) {
                            int i2 = path[j];
                            row4col[j] = (short)i2;
                            int nxt = col4row[i2];
                            col4row[i2] = (short)j;
                            j = nxt;
                            if (i2 == rr) break;
                        }
                    }
                    // ii == rr: row rr simply stays unmatched
                } else {
                    int j = sink;
                    while (true) {
                        int i2 = path[j];
                        row4col[j] = (short)i2;
                        int nxt = col4row[i2];
                        col4row[i2] = (short)j;
                        j = nxt;
                        if (i2 == rr) break;
                    }
                }
            }
            __syncwarp();
        }
    }
    __syncthreads();

    // ---- outputs (float32): out[0:n]=row, out[n:n+m]=col, default -1 ----
    for (int x = tid; x < n + m; x += NTH) out[x] = -1.0f;
    __syncthreads();
    for (int r = tid; r < nr; r += NTH) {
        int j = col4row[r];
        if (j >= 0) {
            int oi = rowlist[r], oj = colmap[j];
            out[oi] = (float)oj;
            out[n + oj] = (float)oi;
        }
    }
}

extern "C" void kernel_launch(void* const* d_in, const int* in_sizes, int n_in,
                              void* d_out, int out_size) {
    const float* tgt = (const float*)d_in[0];   // target_bbox   [N,4] fp32
    const float* prp = (const float*)d_in[1];   // proposal_bbox [M,4] fp32
    int N = in_sizes[0] / 4;
    int M = in_sizes[1] / 4;
    matcher_kernel<<<1, NTH>>>(tgt, prp, N, M, (float*)d_out);
}

// round 5
// speedup vs baseline: 1653.0379x; 2.0290x over previous
#include <cuda_runtime.h>
#include <math_constants.h>

#define NTH   1024
#define NMAX  128
#define MMAX  320
#define ECAP  2048      // shared-memory edge capacity
#define MAXE  30720     // >= n*m worst case
#define FULLMASK 0xffffffffu

// global fallback storage (no allocations allowed)
__device__ int   g_eij[MAXE];
__device__ float g_ew[MAXE];
__device__ short g_ccol[MAXE];
__device__ float g_cw[MAXE];

// Fused: exact fp32 IoU -> sparse IoU>0.5 edges -> CSR -> greedy JV init ->
// exact fp64 successive-shortest-path min-cost matching with aggregated dummy
// sink (== lap.lapjv(C, cost_limit=-0.5, extend_cost=True) restricted to real
// pairs; optimum unique a.s. so any exact solver reproduces the reference).
__global__ void __launch_bounds__(NTH, 1)
matcher_kernel(const float* __restrict__ tgt, const float* __restrict__ prp,
               int n, int m, float* __restrict__ out) {
    __shared__ int   s_eij[ECAP];
    __shared__ float s_ew[ECAP];
    __shared__ short cs_col[ECAP];
    __shared__ float cs_w[ECAP];
    __shared__ int   cs_off[NMAX + 1];
    __shared__ int   deg[NMAX];
    __shared__ int   cur_off[NMAX];
    __shared__ unsigned char colhas[MMAX];
    __shared__ short colmap[MMAX], cinv[MMAX];
    __shared__ short rowlist[NMAX], bestcol[NMAX];
    __shared__ double u[NMAX], v[MMAX], spc[MMAX];
    __shared__ short path[MMAX], row4col[MMAX];
    __shared__ short col4row[NMAX];
    __shared__ unsigned char SC[MMAX];
    __shared__ short srl[NMAX];
    __shared__ int s_ne, s_nr, s_mp;

    const int tid = threadIdx.x;

    if (tid == 0) s_ne = 0;
    for (int x = tid; x < m; x += NTH) colhas[x] = 0;
    for (int x = tid; x < n; x += NTH) deg[x] = 0;
    __syncthreads();

    // ---- phase 1: exact fp32 IoU, emit IoU>0.5 edges ----
    const int nm = n * m;
    for (int idx = tid; idx < nm; idx += NTH) {
        int i = idx / m, j = idx - i * m;
        float ax0 = __ldg(&tgt[4 * i + 0]), ay0 = __ldg(&tgt[4 * i + 1]);
        float ax1 = __ldg(&tgt[4 * i + 2]), ay1 = __ldg(&tgt[4 * i + 3]);
        float bx0 = __ldg(&prp[4 * j + 0]), by0 = __ldg(&prp[4 * j + 1]);
        float bx1 = __ldg(&prp[4 * j + 2]), by1 = __ldg(&prp[4 * j + 3]);

        // round-to-nearest intrinsics block FMA contraction: bits match reference
        float area_a = __fmul_rn(__fsub_rn(ax1, ax0), __fsub_rn(ay1, ay0));
        float area_b = __fmul_rn(__fsub_rn(bx1, bx0), __fsub_rn(by1, by0));
        float ltx = fmaxf(ax0, bx0), lty = fmaxf(ay0, by0);
        float rbx = fminf(ax1, bx1), rby = fminf(ay1, by1);
        float wx = fmaxf(__fsub_rn(rbx, ltx), 0.0f);
        float wy = fmaxf(__fsub_rn(rby, lty), 0.0f);
        float inter = __fmul_rn(wx, wy);
        float uni = __fsub_rn(__fadd_rn(area_a, area_b), inter);
        float iou = __fdiv_rn(inter, uni);

        if (iou > 0.5f) {
            int pos = atomicAdd(&s_ne, 1);
            int pack = (i << 16) | j;
            if (pos < ECAP) { s_eij[pos] = pack; s_ew[pos] = -iou; }
            if (pos < MAXE) { g_eij[pos] = pack; g_ew[pos] = -iou; }
            atomicAdd(&deg[i], 1);
            colhas[j] = 1;
        }
    }
    __syncthreads();

    const int E = s_ne;
    const bool small = (E <= ECAP);

    // ---- parallel compaction: warp 0 = columns, warp 1 = rows + CSR offsets ----
    if (tid < 32) {
        int base = 0;
        for (int c = 0; c < m; c += 32) {
            int j = c + tid;
            bool f = (j < m) && colhas[j];
            unsigned mask = __ballot_sync(FULLMASK, f);
            int pos = base + __popc(mask & ((1u << tid) - 1));
            if (f) { cinv[j] = (short)pos; colmap[pos] = (short)j; }
            base += __popc(mask);
        }
        if (tid == 0) s_mp = base;
    } else if (tid < 64) {
        int lane = tid - 32;
        int rbase = 0, obase = 0;
        for (int c = 0; c < n; c += 32) {
            int i = c + lane;
            int d = (i < n) ? deg[i] : 0;
            bool f = d > 0;
            unsigned mask = __ballot_sync(FULLMASK, f);
            int rpos = rbase + __popc(mask & ((1u << lane) - 1));
            if (f) rowlist[rpos] = (short)i;
            rbase += __popc(mask);
            int incl = d;
            #pragma unroll
            for (int off = 1; off < 32; off <<= 1) {
                int t = __shfl_up_sync(FULLMASK, incl, off);
                if (lane >= off) incl += t;
            }
            int excl = obase + incl - d;
            if (i < n) { cs_off[i] = excl; cur_off[i] = excl; }
            obase += __shfl_sync(FULLMASK, incl, 31);
        }
        if (lane == 0) { s_nr = rbase; cs_off[n] = obase; }
    }
    // default outputs (independent of solver)
    for (int x = tid; x < n + m; x += NTH) out[x] = -1.0f;
    __syncthreads();
    const int mp = s_mp, nr = s_nr;

    // ---- CSR scatter (all threads) ----
    if (small) {
        for (int e = tid; e < E; e += NTH) {
            int pk = s_eij[e]; int i = pk >> 16, j = pk & 0xffff;
            int p = atomicAdd(&cur_off[i], 1);
            cs_col[p] = cinv[j]; cs_w[p] = s_ew[e];
        }
    } else {
        int EE = (E > MAXE) ? MAXE : E;
        for (int e = tid; e < EE; e += NTH) {
            int pk = g_eij[e]; int i = pk >> 16, j = pk & 0xffff;
            int p = atomicAdd(&cur_off[i], 1);
            g_ccol[p] = cinv[j]; g_cw[p] = g_ew[e];
        }
    }
    __syncthreads();

    // ---- exact fp64 SSP min-cost matching (warp 0) ----
    if (tid < 32) {
        const short* Ccol = small ? cs_col : g_ccol;
        const float* Cw   = small ? cs_w   : g_cw;

        // greedy JV init: u[i] = min_j w_ij (feasible; dummy redcost -u_i >= 0),
        // assign row to its argmin column if free. SSP from a feasible dual +
        // complementary partial matching is still exact.
        for (int rr = tid; rr < nr; rr += 32) {
            int io = rowlist[rr];
            int b = cs_off[io], e2 = cs_off[io + 1];
            float bw = 1e30f; int bj = 0x7fff;
            for (int e = b; e < e2; ++e) {
                float w = Cw[e]; int j = Ccol[e];
                if (w < bw || (w == bw && j < bj)) { bw = w; bj = j; }
            }
            u[rr] = (double)bw + 0.5;
            bestcol[rr] = (short)bj;
            col4row[rr] = -1;
        }
        for (int x = tid; x < mp; x += 32) { v[x] = 0.0; row4col[x] = -1; }
        __syncwarp();
        if (tid == 0) {
            for (int rr = 0; rr < nr; ++rr) {
                int j = bestcol[rr];
                if (row4col[j] < 0) { row4col[j] = (short)rr; col4row[rr] = (short)j; }
            }
        }
        __syncwarp();

        for (int rr = 0; rr < nr; ++rr) {
            if (col4row[rr] >= 0) continue;   // satisfied by greedy init

            for (int x = tid; x < mp; x += 32) {
                spc[x] = CUDART_INF; SC[x] = 0; path[x] = -1;
            }
            __syncwarp();

            int i = rr;                     // compact row index (uniform)
            double shortest = 0.0;
            double spcD = CUDART_INF;       // label of aggregated dummy sink
            int dpred = -1;
            int nsr = 0;
            int sink = -1;
            double minVal = 0.0;
            bool dummySink = false;

            while (true) {
                if (tid == 0) srl[nsr] = (short)i;
                nsr++;
                const double ui = u[i];

                // dummy ("stay unmatched") relax: w=0, v_dummy=0
                double dc = shortest - ui;
                if (dc < spcD) { spcD = dc; dpred = i; }

                // relax this row's edges (CSR)
                int io = rowlist[i];
                int b = cs_off[io], e2 = cs_off[io + 1];
                for (int e = b + tid; e < e2; e += 32) {
                    int j = Ccol[e];
                    if (!SC[j]) {
                        double red = shortest + ((double)Cw[e] + 0.5) - ui - v[j];
                        if (red < spc[j]) { spc[j] = red; path[j] = (short)i; }
                    }
                }
                __syncwarp();

                // argmin over unscanned columns
                double best = CUDART_INF; int bidx = 0x7fffffff;
                for (int j = tid; j < mp; j += 32)
                    if (!SC[j] && spc[j] < best) { best = spc[j]; bidx = j; }
                #pragma unroll
                for (int off = 16; off; off >>= 1) {
                    double ob = __shfl_xor_sync(FULLMASK, best, off);
                    int oi = __shfl_xor_sync(FULLMASK, bidx, off);
                    if (ob < best || (ob == best && oi < bidx)) { best = ob; bidx = oi; }
                }

                if (spcD < best) { dummySink = true; minVal = spcD; break; }
                minVal = best;
                if (tid == 0) SC[bidx] = 1;
                __syncwarp();
                int r4 = row4col[bidx];
                if (r4 < 0) { sink = bidx; break; }
                i = r4;
                shortest = minVal;
            }
            __syncwarp();

            // dual updates (JV form; keeps dummy edges feasible: u[i] <= 0)
            for (int t = tid; t < nsr; t += 32) {
                int ii = srl[t];
                if (ii == rr) u[ii] += minVal;
                else          u[ii] += minVal - spc[col4row[ii]];
            }
            for (int j = tid; j < mp; j += 32)
                if (SC[j]) v[j] -= minVal - spc[j];
            __syncwarp();

            // augment (lane 0, integer-only)
            if (tid == 0) {
                if (dummySink) {
                    int ii = dpred;
                    if (ii != rr) {
                        int j = col4row[ii];
                        col4row[ii] = -1;       // ii becomes unmatched
                        while (true) {
                            int i2 = path[j];
                            row4col[j] = (short)i2;
                            int nxt = col4row[i2];
                            col4row[i2] = (short)j;
                            j = nxt;
                            if (i2 == rr) break;
                        }
                    }
                    // ii == rr: row rr simply stays unmatched
                } else {
                    int j = sink;
                    while (true) {
                        int i2 = path[j];
                        row4col[j] = (short)i2;
                        int nxt = col4row[i2];
                        col4row[i2] = (short)j;
                        j = nxt;
                        if (i2 == rr) break;
                    }
                }
            }
            __syncwarp();
        }
    }
    __syncthreads();

    // ---- matched outputs (defaults written earlier) ----
    for (int r = tid; r < nr; r += NTH) {
        int j = col4row[r];
        if (j >= 0) {
            int oi = rowlist[r], oj = colmap[j];
            out[oi] = (float)oj;
            out[n + oj] = (float)oi;
        }
    }
}

extern "C" void kernel_launch(void* const* d_in, const int* in_sizes, int n_in,
                              void* d_out, int out_size) {
    const float* tgt = (const float*)d_in[0];   // target_bbox   [N,4] fp32
    const float* prp = (const float*)d_in[1];   // proposal_bbox [M,4] fp32
    int N = in_sizes[0] / 4;
    int M = in_sizes[1] / 4;
    matcher_kernel<<<1, NTH>>>(tgt, prp, N, M, (float*)d_out);
}

// round 6
// speedup vs baseline: 3258.8461x; 1.9714x over previous
#include <cuda_runtime.h>
#include <math_constants.h>

#define STH   256       // solver block threads
#define NMAX  128
#define MMAX  320
#define ECAP  2048      // shared-memory edge capacity
#define MAXE  30720     // >= n*m worst case
#define FULLMASK 0xffffffffu

// device globals (no allocation allowed)
__device__ int   g_ne;
__device__ int   g_eij[MAXE];
__device__ float g_ew[MAXE];
__device__ short g_ccol[MAXE];   // fallback CSR (E > ECAP)
__device__ float g_cw[MAXE];

// ---- phase 1 (grid-wide): exact fp32 IoU, one pair per thread ----
__global__ void iou_edge_kernel(const float* __restrict__ tgt,
                                const float* __restrict__ prp,
                                int N, int M) {
    int idx = blockIdx.x * blockDim.x + threadIdx.x;
    if (idx >= N * M) return;
    int i = idx / M, j = idx - i * M;

    float ax0 = __ldg(&tgt[4 * i + 0]), ay0 = __ldg(&tgt[4 * i + 1]);
    float ax1 = __ldg(&tgt[4 * i + 2]), ay1 = __ldg(&tgt[4 * i + 3]);
    float bx0 = __ldg(&prp[4 * j + 0]), by0 = __ldg(&prp[4 * j + 1]);
    float bx1 = __ldg(&prp[4 * j + 2]), by1 = __ldg(&prp[4 * j + 3]);

    // round-to-nearest intrinsics block FMA contraction: bits match reference
    float area_a = __fmul_rn(__fsub_rn(ax1, ax0), __fsub_rn(ay1, ay0));
    float area_b = __fmul_rn(__fsub_rn(bx1, bx0), __fsub_rn(by1, by0));
    float ltx = fmaxf(ax0, bx0), lty = fmaxf(ay0, by0);
    float rbx = fminf(ax1, bx1), rby = fminf(ay1, by1);
    float wx = fmaxf(__fsub_rn(rbx, ltx), 0.0f);
    float wy = fmaxf(__fsub_rn(rby, lty), 0.0f);
    float inter = __fmul_rn(wx, wy);
    float uni = __fsub_rn(__fadd_rn(area_a, area_b), inter);
    float iou = __fdiv_rn(inter, uni);

    // Only IoU>0.5 pairs can appear in the padded lapjv(cost_limit=-0.5)
    // optimum; everything else is provably unmatched.
    if (iou > 0.5f) {
        int pos = atomicAdd(&g_ne, 1);
        if (pos < MAXE) {
            g_eij[pos] = (i << 16) | j;
            g_ew[pos] = -iou;        // C_ij, exact fp32
        }
    }
}

// ---- phase 2 (1 block): CSR build + greedy JV init + exact fp64 SSP ----
// (== lap.lapjv(C, cost_limit=-0.5, extend_cost=True) restricted to real
// pairs; optimum unique a.s., all tie-breaks are order-independent.)
__global__ void __launch_bounds__(STH, 1)
solve_kernel(int n, int m, float* __restrict__ out) {
    __shared__ int   s_eij[ECAP];
    __shared__ float s_ew[ECAP];
    __shared__ short cs_col[ECAP];
    __shared__ float cs_w[ECAP];
    __shared__ int   cs_off[NMAX + 1];
    __shared__ int   deg[NMAX];
    __shared__ int   cur_off[NMAX];
    __shared__ unsigned char colhas[MMAX];
    __shared__ short colmap[MMAX], cinv[MMAX];
    __shared__ short rowlist[NMAX], bestcol[NMAX];
    __shared__ double u[NMAX], v[MMAX], spc[MMAX];
    __shared__ short path[MMAX], row4col[MMAX];
    __shared__ short col4row[NMAX];
    __shared__ unsigned char SC[MMAX];
    __shared__ short srl[NMAX];
    __shared__ int s_nr, s_mp;

    const int tid = threadIdx.x;

    int Eg = g_ne; if (Eg > MAXE) Eg = MAXE;
    const int E = Eg;
    const bool small = (E <= ECAP);

    for (int x = tid; x < m; x += STH) colhas[x] = 0;
    for (int x = tid; x < n; x += STH) deg[x] = 0;
    for (int x = tid; x < n + m; x += STH) out[x] = -1.0f;  // defaults
    __syncthreads();

    // load edges to shared + histogram rows/flag cols
    for (int e = tid; e < E; e += STH) {
        int pk = g_eij[e];
        int i = pk >> 16, j = pk & 0xffff;
        if (small) { s_eij[e] = pk; s_ew[e] = g_ew[e]; }
        atomicAdd(&deg[i], 1);
        colhas[j] = 1;
    }
    __syncthreads();

    // ---- parallel compaction: warp 0 = columns, warp 1 = rows + CSR offsets ----
    if (tid < 32) {
        int base = 0;
        for (int c = 0; c < m; c += 32) {
            int j = c + tid;
            bool f = (j < m) && colhas[j];
            unsigned mask = __ballot_sync(FULLMASK, f);
            int pos = base + __popc(mask & ((1u << tid) - 1));
            if (f) { cinv[j] = (short)pos; colmap[pos] = (short)j; }
            base += __popc(mask);
        }
        if (tid == 0) s_mp = base;
    } else if (tid < 64) {
        int lane = tid - 32;
        int rbase = 0, obase = 0;
        for (int c = 0; c < n; c += 32) {
            int i = c + lane;
            int d = (i < n) ? deg[i] : 0;
            bool f = d > 0;
            unsigned mask = __ballot_sync(FULLMASK, f);
            int rpos = rbase + __popc(mask & ((1u << lane) - 1));
            if (f) rowlist[rpos] = (short)i;
            rbase += __popc(mask);
            int incl = d;
            #pragma unroll
            for (int off = 1; off < 32; off <<= 1) {
                int t = __shfl_up_sync(FULLMASK, incl, off);
                if (lane >= off) incl += t;
            }
            int excl = obase + incl - d;
            if (i < n) { cs_off[i] = excl; cur_off[i] = excl; }
            obase += __shfl_sync(FULLMASK, incl, 31);
        }
        if (lane == 0) { s_nr = rbase; cs_off[n] = obase; }
    }
    __syncthreads();
    const int mp = s_mp, nr = s_nr;

    // ---- CSR scatter ----
    if (small) {
        for (int e = tid; e < E; e += STH) {
            int pk = s_eij[e]; int i = pk >> 16, j = pk & 0xffff;
            int p = atomicAdd(&cur_off[i], 1);
            cs_col[p] = cinv[j]; cs_w[p] = s_ew[e];
        }
    } else {
        for (int e = tid; e < E; e += STH) {
            int pk = g_eij[e]; int i = pk >> 16, j = pk & 0xffff;
            int p = atomicAdd(&cur_off[i], 1);
            g_ccol[p] = cinv[j]; g_cw[p] = g_ew[e];
        }
    }
    __syncthreads();

    // ---- exact fp64 SSP min-cost matching (warp 0) ----
    if (tid < 32) {
        const short* Ccol = small ? cs_col : g_ccol;
        const float* Cw   = small ? cs_w   : g_cw;

        // greedy JV init: u[i] = min_j w_ij (feasible; dummy redcost -u_i >= 0),
        // assign row to its argmin column if free.
        for (int rr = tid; rr < nr; rr += 32) {
            int io = rowlist[rr];
            int b = cs_off[io], e2 = cs_off[io + 1];
            float bw = 1e30f; int bj = 0x7fff;
            for (int e = b; e < e2; ++e) {
                float w = Cw[e]; int j = Ccol[e];
                if (w < bw || (w == bw && j < bj)) { bw = w; bj = j; }
            }
            u[rr] = (double)bw + 0.5;
            bestcol[rr] = (short)bj;
            col4row[rr] = -1;
        }
        for (int x = tid; x < mp; x += 32) { v[x] = 0.0; row4col[x] = -1; }
        __syncwarp();
        if (tid == 0) {
            for (int rr = 0; rr < nr; ++rr) {
                int j = bestcol[rr];
                if (row4col[j] < 0) { row4col[j] = (short)rr; col4row[rr] = (short)j; }
            }
        }
        __syncwarp();

        for (int rr = 0; rr < nr; ++rr) {
            if (col4row[rr] >= 0) continue;   // satisfied by greedy init

            for (int x = tid; x < mp; x += 32) {
                spc[x] = CUDART_INF; SC[x] = 0; path[x] = -1;
            }
            __syncwarp();

            int i = rr;
            double shortest = 0.0;
            double spcD = CUDART_INF;       // aggregated dummy sink label
            int dpred = -1;
            int nsr = 0;
            int sink = -1;
            double minVal = 0.0;
            bool dummySink = false;

            while (true) {
                if (tid == 0) srl[nsr] = (short)i;
                nsr++;
                const double ui = u[i];

                // dummy ("stay unmatched") relax: w=0, v_dummy=0
                double dc = shortest - ui;
                if (dc < spcD) { spcD = dc; dpred = i; }

                // relax this row's edges (CSR)
                int io = rowlist[i];
                int b = cs_off[io], e2 = cs_off[io + 1];
                for (int e = b + tid; e < e2; e += 32) {
                    int j = Ccol[e];
                    if (!SC[j]) {
                        double red = shortest + ((double)Cw[e] + 0.5) - ui - v[j];
                        if (red < spc[j]) { spc[j] = red; path[j] = (short)i; }
                    }
                }
                __syncwarp();

                // argmin over unscanned columns
                double best = CUDART_INF; int bidx = 0x7fffffff;
                for (int j = tid; j < mp; j += 32)
                    if (!SC[j] && spc[j] < best) { best = spc[j]; bidx = j; }
                #pragma unroll
                for (int off = 16; off; off >>= 1) {
                    double ob = __shfl_xor_sync(FULLMASK, best, off);
                    int oi = __shfl_xor_sync(FULLMASK, bidx, off);
                    if (ob < best || (ob == best && oi < bidx)) { best = ob; bidx = oi; }
                }

                if (spcD < best) { dummySink = true; minVal = spcD; break; }
                minVal = best;
                if (tid == 0) SC[bidx] = 1;
                __syncwarp();
                int r4 = row4col[bidx];
                if (r4 < 0) { sink = bidx; break; }
                i = r4;
                shortest = minVal;
            }
            __syncwarp();

            // dual updates (JV form; keeps dummy edges feasible: u[i] <= 0)
            for (int t = tid; t < nsr; t += 32) {
                int ii = srl[t];
                if (ii == rr) u[ii] += minVal;
                else          u[ii] += minVal - spc[col4row[ii]];
            }
            for (int j = tid; j < mp; j += 32)
                if (SC[j]) v[j] -= minVal - spc[j];
            __syncwarp();

            // augment (lane 0, integer-only)
            if (tid == 0) {
                if (dummySink) {
                    int ii = dpred;
                    if (ii != rr) {
                        int j = col4row[ii];
                        col4row[ii] = -1;       // ii becomes unmatched
                        while (true) {
                            int i2 = path[j];
                            row4col[j] = (short)i2;
                            int nxt = col4row[i2];
                            col4row[i2] = (short)j;
                            j = nxt;
                            if (i2 == rr) break;
                        }
                    }
                } else {
                    int j = sink;
                    while (true) {
                        int i2 = path[j];
                        row4col[j] = (short)i2;
                        int nxt = col4row[i2];
                        col4row[i2] = (short)j;
                        j = nxt;
                        if (i2 == rr) break;
                    }
                }
            }
            __syncwarp();
        }
    }
    __syncthreads();

    // ---- matched outputs (defaults were written above) ----
    for (int r = tid; r < nr; r += STH) {
        int j = col4row[r];
        if (j >= 0) {
            int oi = rowlist[r], oj = colmap[j];
            out[oi] = (float)oj;
            out[n + oj] = (float)oi;
        }
    }
}

extern "C" void kernel_launch(void* const* d_in, const int* in_sizes, int n_in,
                              void* d_out, int out_size) {
    const float* tgt = (const float*)d_in[0];   // target_bbox   [N,4] fp32
    const float* prp = (const float*)d_in[1];   // proposal_bbox [M,4] fp32
    int N = in_sizes[0] / 4;
    int M = in_sizes[1] / 4;
    int nm = N * M;

    // reset edge counter (graph-capturable memset node; no allocation)
    void* ne_ptr = nullptr;
    cudaGetSymbolAddress(&ne_ptr, g_ne);
    cudaMemsetAsync(ne_ptr, 0, sizeof(int));

    iou_edge_kernel<<<(nm + 255) / 256, 256>>>(tgt, prp, N, M);
    solve_kernel<<<1, STH>>>(N, M, (float*)d_out);
}